// round 15
// baseline (speedup 1.0000x reference)
#include <cuda_runtime.h>
#include <cuda_bf16.h>
#include <cstdint>
#include <math.h>

#define NB 8
#define HWN 1024
#define CD 128
#define NF 900
#define FSZ 9
#define EPSV 1e-5f
#define ROWB 272          // padded row stride in bytes (136 bf16) -> conflict-free ldmatrix
#define NBAND 25
#define WPB 4             // windows per out-block

// ---------------- scratch (device globals; allocation forbidden) ------------
__device__ __nv_bfloat16 g_Wqh[CD * CD];
__device__ __nv_bfloat16 g_Wql[CD * CD];
__device__ __nv_bfloat16 g_Wkh[CD * CD];
__device__ __nv_bfloat16 g_Wkl[CD * CD];
__device__ __nv_bfloat16 g_Qh[NB * HWN * CD];
__device__ __nv_bfloat16 g_Ql[NB * HWN * CD];
__device__ __nv_bfloat16 g_Kh[NB * HWN * CD];
__device__ __nv_bfloat16 g_Kl[NB * HWN * CD];
__device__ float  g_V[NB * HWN];
__device__ float  g_band[NB * NBAND * HWN];      // exp(S[p, p+delta]) banded, 800KB
__device__ double g_E[NB * HWN];
__device__ double g_G[NB * HWN];

// ---- proj smem layout (128x128 tiles), total 147456, 1 CTA/SM ----
#define PTILEB (128 * ROWB)
#define PSM_AUX  0
#define PSM_AH   8192
#define PSM_AL   (PSM_AH + PTILEB)
#define PSM_BH   (PSM_AL + PTILEB)
#define PSM_BL   (PSM_BH + PTILEB)
#define PSM_TOTAL (PSM_BL + PTILEB)

// ---- gemm_s smem layout (A 64-row, B 128-row), total 108544 -> 2 CTA/SM ----
#define ATILEB (64 * ROWB)
#define BTILEB (128 * ROWB)
#define SSM_AUX  0
#define SSM_ERED 512
#define SSM_GRED (SSM_ERED + 64 * 4 * 4)
#define SSM_AH   4096
#define SSM_AL   (SSM_AH + ATILEB)
#define SSM_BH   (SSM_AL + ATILEB)
#define SSM_BL   (SSM_BH + BTILEB)
#define SSM_TOTAL (SSM_BL + BTILEB)

extern __shared__ char smx[];

// ---------------- helpers ----------------------------------------------------
__device__ __forceinline__ uint32_t smem_u32(const void* p) {
    uint32_t a;
    asm("{ .reg .u64 t; cvta.to.shared.u64 t, %1; cvt.u32.u64 %0, t; }" : "=r"(a) : "l"(p));
    return a;
}
__device__ __forceinline__ void ldsm4(uint32_t* r, uint32_t addr) {
    asm volatile("ldmatrix.sync.aligned.m8n8.x4.shared.b16 {%0,%1,%2,%3}, [%4];"
                 : "=r"(r[0]), "=r"(r[1]), "=r"(r[2]), "=r"(r[3]) : "r"(addr));
}
__device__ __forceinline__ void ldsm2(uint32_t* r, uint32_t addr) {
    asm volatile("ldmatrix.sync.aligned.m8n8.x2.shared.b16 {%0,%1}, [%2];"
                 : "=r"(r[0]), "=r"(r[1]) : "r"(addr));
}
__device__ __forceinline__ void mma_bf16(float* d, const uint32_t* a, const uint32_t* b) {
    asm volatile("mma.sync.aligned.m16n8k16.row.col.f32.bf16.bf16.f32 "
                 "{%0,%1,%2,%3}, {%4,%5,%6,%7}, {%8,%9}, {%0,%1,%2,%3};"
                 : "+f"(d[0]), "+f"(d[1]), "+f"(d[2]), "+f"(d[3])
                 : "r"(a[0]), "r"(a[1]), "r"(a[2]), "r"(a[3]), "r"(b[0]), "r"(b[1]));
}

// sync copy (proj): [128][128] bf16 tile into padded smem
__device__ __forceinline__ void copy_tile(char* sm, const __nv_bfloat16* __restrict__ src, int tid) {
#pragma unroll
    for (int j = 0; j < 8; j++) {
        int idx = tid + j * 256;
        int row = idx >> 4;
        int c   = idx & 15;
        uint4 v = reinterpret_cast<const uint4*>(src + (size_t)row * CD)[c];
        *reinterpret_cast<uint4*>(sm + row * ROWB + c * 16) = v;
    }
}

// async copy (gemm_s): [rows][128] bf16 tile into padded smem via cp.async
__device__ __forceinline__ void copy_tile_async(uint32_t smdst, const __nv_bfloat16* __restrict__ src,
                                                int rows, int tid) {
    int chunks = rows * 16;
    for (int j = tid; j < chunks; j += 256) {
        int row = j >> 4, c = j & 15;
        uint32_t d = smdst + row * ROWB + c * 16;
        const void* g = src + (size_t)row * CD + c * 8;
        asm volatile("cp.async.cg.shared.global [%0], [%1], 16;" :: "r"(d), "l"(g));
    }
}

// ---------------- proj mainloop: 128x128 tiles, warp tile 64x32 --------------
__device__ __forceinline__ void mma_triple128(uint32_t sb, int wm, int wn, int lane,
                                              float acc[4][4][4]) {
    uint32_t arow = (wm * 64 + (lane & 15)) * ROWB + (lane >> 4) * 16;
    uint32_t brow = (wn * 32 + (lane & 7)) * ROWB + ((lane >> 3) & 1) * 16;
    uint32_t ah_b = sb + PSM_AH + arow, al_b = sb + PSM_AL + arow;
    uint32_t bh_b = sb + PSM_BH + brow, bl_b = sb + PSM_BL + brow;
#pragma unroll
    for (int kk = 0; kk < 8; kk++) {
        uint32_t kb = kk * 32;
        uint32_t ah[4][4], al[4][4], bh[4][2], bl[4][2];
#pragma unroll
        for (int mt = 0; mt < 4; mt++) {
            ldsm4(ah[mt], ah_b + mt * 16 * ROWB + kb);
            ldsm4(al[mt], al_b + mt * 16 * ROWB + kb);
        }
#pragma unroll
        for (int nt = 0; nt < 4; nt++) {
            ldsm2(bh[nt], bh_b + nt * 8 * ROWB + kb);
            ldsm2(bl[nt], bl_b + nt * 8 * ROWB + kb);
        }
#pragma unroll
        for (int mt = 0; mt < 4; mt++)
#pragma unroll
            for (int nt = 0; nt < 4; nt++) {
                mma_bf16(acc[mt][nt], ah[mt], bh[nt]);
                mma_bf16(acc[mt][nt], ah[mt], bl[nt]);
                mma_bf16(acc[mt][nt], al[mt], bh[nt]);
            }
    }
}

// ---------------- gemm_s mainloop: A 64-row, warp tile 32x32, merged 3-term --
__device__ __forceinline__ void mma_triple64(uint32_t sb, int wm, int wn, int lane,
                                             float acc[2][4][4]) {
    uint32_t arow = (wm * 32 + (lane & 15)) * ROWB + (lane >> 4) * 16;
    uint32_t brow = (wn * 32 + (lane & 7)) * ROWB + ((lane >> 3) & 1) * 16;
    uint32_t ah_b = sb + SSM_AH + arow, al_b = sb + SSM_AL + arow;
    uint32_t bh_b = sb + SSM_BH + brow, bl_b = sb + SSM_BL + brow;
#pragma unroll
    for (int kk = 0; kk < 8; kk++) {
        uint32_t kb = kk * 32;
        uint32_t ah[2][4], al[2][4], bh[4][2], bl[4][2];
#pragma unroll
        for (int mt = 0; mt < 2; mt++) {
            ldsm4(ah[mt], ah_b + mt * 16 * ROWB + kb);
            ldsm4(al[mt], al_b + mt * 16 * ROWB + kb);
        }
#pragma unroll
        for (int nt = 0; nt < 4; nt++) {
            ldsm2(bh[nt], bh_b + nt * 8 * ROWB + kb);
            ldsm2(bl[nt], bl_b + nt * 8 * ROWB + kb);
        }
#pragma unroll
        for (int mt = 0; mt < 2; mt++)
#pragma unroll
            for (int nt = 0; nt < 4; nt++) {
                mma_bf16(acc[mt][nt], ah[mt], bh[nt]);
                mma_bf16(acc[mt][nt], ah[mt], bl[nt]);
                mma_bf16(acc[mt][nt], al[mt], bh[nt]);
            }
    }
}

// ---------------- small prep: split W, zero E/G ------------------------------
__global__ void prep_kernel(const float* __restrict__ Wq, const float* __restrict__ Wk) {
    int blk = blockIdx.x;
    int t = threadIdx.x;
    if (blk < 64) {
        int i = blk * 256 + t;
        float v = Wq[i];
        __nv_bfloat16 h = __float2bfloat16(v);
        g_Wqh[i] = h;
        g_Wql[i] = __float2bfloat16(v - __bfloat162float(h));
    } else if (blk < 128) {
        int i = (blk - 64) * 256 + t;
        float v = Wk[i];
        __nv_bfloat16 h = __float2bfloat16(v);
        g_Wkh[i] = h;
        g_Wkl[i] = __float2bfloat16(v - __bfloat162float(h));
    } else {
        int i = (blk - 128) * 256 + t;
        g_E[i] = 0.0;
        g_G[i] = 0.0;
    }
}

// ---------------- projection GEMM (fp32 in, inline split, fused V) -----------
// blockIdx.x: row tile (64), blockIdx.y: 0 = Q (computes V), 1 = K
__global__ __launch_bounds__(256, 1) void gemm_proj_tc(const float* __restrict__ batch,
                                                       const float* __restrict__ bq,
                                                       const float* __restrict__ bk,
                                                       const float* __restrict__ wv,
                                                       const float* __restrict__ bv) {
    uint32_t sb = smem_u32(smx);
    int tid = threadIdx.x;
    int wid = tid >> 5, lane = tid & 31;
    int wm = wid & 1, wn = wid >> 1;
    int row0 = blockIdx.x * 128;
    bool isK = blockIdx.y != 0;

    const __nv_bfloat16* Wh = isK ? g_Wkh : g_Wqh;
    const __nv_bfloat16* Wl = isK ? g_Wkl : g_Wql;
    const float* bias = isK ? bk : bq;
    __nv_bfloat16* Oh = isK ? g_Kh : g_Qh;
    __nv_bfloat16* Ol = isK ? g_Kl : g_Ql;

    const float* xsrc = batch + (size_t)row0 * CD;
    float4 wv4;
    if (!isK) wv4 = reinterpret_cast<const float4*>(wv)[lane];
#pragma unroll
    for (int j = 0; j < 16; j++) {
        int idx = tid + j * 256;
        int row = idx >> 5;
        int c4  = idx & 31;
        float4 v = reinterpret_cast<const float4*>(xsrc + (size_t)row * CD)[c4];
        __nv_bfloat16 h0 = __float2bfloat16(v.x), h1 = __float2bfloat16(v.y);
        __nv_bfloat16 h2 = __float2bfloat16(v.z), h3 = __float2bfloat16(v.w);
        __nv_bfloat162 ph0, ph1, pl0, pl1;
        ph0.x = h0; ph0.y = h1; ph1.x = h2; ph1.y = h3;
        pl0.x = __float2bfloat16(v.x - __bfloat162float(h0));
        pl0.y = __float2bfloat16(v.y - __bfloat162float(h1));
        pl1.x = __float2bfloat16(v.z - __bfloat162float(h2));
        pl1.y = __float2bfloat16(v.w - __bfloat162float(h3));
        uint2 hh, ll;
        hh.x = *reinterpret_cast<uint32_t*>(&ph0); hh.y = *reinterpret_cast<uint32_t*>(&ph1);
        ll.x = *reinterpret_cast<uint32_t*>(&pl0); ll.y = *reinterpret_cast<uint32_t*>(&pl1);
        *reinterpret_cast<uint2*>(smx + PSM_AH + row * ROWB + c4 * 8) = hh;
        *reinterpret_cast<uint2*>(smx + PSM_AL + row * ROWB + c4 * 8) = ll;
        if (!isK) {
            float s = v.x * wv4.x + v.y * wv4.y + v.z * wv4.z + v.w * wv4.w;
#pragma unroll
            for (int off = 16; off; off >>= 1) s += __shfl_xor_sync(0xffffffffu, s, off);
            if (lane == 0) g_V[row0 + row] = s + bv[0];
        }
    }
    copy_tile(smx + PSM_BH, Wh, tid);
    copy_tile(smx + PSM_BL, Wl, tid);
    if (tid < 128) *reinterpret_cast<float*>(smx + PSM_AUX + tid * 4) = bias[tid];
    __syncthreads();

    float acc[4][4][4];
#pragma unroll
    for (int mt = 0; mt < 4; mt++)
#pragma unroll
        for (int nt = 0; nt < 4; nt++)
#pragma unroll
            for (int i = 0; i < 4; i++) acc[mt][nt][i] = 0.f;

    mma_triple128(sb, wm, wn, lane, acc);

    const float* bs = reinterpret_cast<const float*>(smx + PSM_AUX);
#pragma unroll
    for (int mt = 0; mt < 4; mt++) {
        int rlo = row0 + wm * 64 + mt * 16 + (lane >> 2);
#pragma unroll
        for (int nt = 0; nt < 4; nt++) {
            int col = wn * 32 + nt * 8 + (lane & 3) * 2;
            float b0 = bs[col], b1 = bs[col + 1];
#pragma unroll
            for (int half = 0; half < 2; half++) {
                int row = rlo + half * 8;
                float v0 = acc[mt][nt][half * 2 + 0] + b0;
                float v1 = acc[mt][nt][half * 2 + 1] + b1;
                __nv_bfloat16 h0 = __float2bfloat16(v0);
                __nv_bfloat16 h1 = __float2bfloat16(v1);
                __nv_bfloat162 ph; ph.x = h0; ph.y = h1;
                __nv_bfloat162 pl;
                pl.x = __float2bfloat16(v0 - __bfloat162float(h0));
                pl.y = __float2bfloat16(v1 - __bfloat162float(h1));
                *reinterpret_cast<uint32_t*>(Oh + (size_t)row * CD + col) =
                    *reinterpret_cast<uint32_t*>(&ph);
                *reinterpret_cast<uint32_t*>(Ol + (size_t)row * CD + col) =
                    *reinterpret_cast<uint32_t*>(&pl);
            }
        }
    }
}

// ---------------- E/G row sums + banded capture; M=64 tile, 2 CTA/SM ---------
// grid (8 qtile, 16 ptile, 8 batch) — R11 structure (best measured)
__global__ __launch_bounds__(256, 2) void gemm_s_tc() {
    uint32_t sb = smem_u32(smx);
    int tid = threadIdx.x;
    int wid = tid >> 5, lane = tid & 31;
    int wm = wid & 1, wn = wid >> 1;
    int b  = blockIdx.z;
    int q0 = blockIdx.x * 128, p0 = blockIdx.y * 64;

    size_t abase = ((size_t)b * HWN + p0) * CD;
    size_t bbase = ((size_t)b * HWN + q0) * CD;
    copy_tile_async(sb + SSM_AH, g_Qh + abase, 64, tid);
    copy_tile_async(sb + SSM_AL, g_Ql + abase, 64, tid);
    copy_tile_async(sb + SSM_BH, g_Kh + bbase, 128, tid);
    copy_tile_async(sb + SSM_BL, g_Kl + bbase, 128, tid);
    asm volatile("cp.async.commit_group;" ::: "memory");
    if (tid < 128) *reinterpret_cast<float*>(smx + SSM_AUX + tid * 4) = g_V[b * HWN + q0 + tid];
    asm volatile("cp.async.wait_group 0;" ::: "memory");
    __syncthreads();

    float acc[2][4][4];
#pragma unroll
    for (int mt = 0; mt < 2; mt++)
#pragma unroll
        for (int nt = 0; nt < 4; nt++)
#pragma unroll
            for (int i = 0; i < 4; i++) acc[mt][nt][i] = 0.f;

    mma_triple64(sb, wm, wn, lane, acc);

    const float* Vs = reinterpret_cast<const float*>(smx + SSM_AUX);
    float* esm = reinterpret_cast<float*>(smx + SSM_ERED);
    float* gsm = reinterpret_cast<float*>(smx + SSM_GRED);
    float* bandb = g_band + (size_t)b * NBAND * HWN;
    int tdiff = q0 - p0;
    bool band_tile = (tdiff >= -194 && tdiff <= 130);

#pragma unroll
    for (int mt = 0; mt < 2; mt++) {
#pragma unroll
        for (int half = 0; half < 2; half++) {
            int p = p0 + wm * 32 + mt * 16 + half * 8 + (lane >> 2);
            float esum = 0.f, gsum = 0.f;
#pragma unroll
            for (int nt = 0; nt < 4; nt++) {
                int col = wn * 32 + nt * 8 + (lane & 3) * 2;
                float e0 = __expf(acc[mt][nt][half * 2 + 0]);
                float e1 = __expf(acc[mt][nt][half * 2 + 1]);
                esum += e0 + e1;
                gsum += e0 * Vs[col] + e1 * Vs[col + 1];
                if (band_tile) {
                    int q = q0 + col;
#pragma unroll
                    for (int u = 0; u < 2; u++) {
                        int d = q + u - p;
                        int di = ((d + 80) >> 5) - 2;
                        int dj = d - di * 32;
                        if (di >= -2 && di <= 2 && dj >= -2 && dj <= 2)
                            bandb[((di + 2) * 5 + dj + 2) * HWN + p] = u ? e1 : e0;
                    }
                }
            }
#pragma unroll
            for (int off = 1; off <= 2; off <<= 1) {
                esum += __shfl_xor_sync(0xffffffffu, esum, off);
                gsum += __shfl_xor_sync(0xffffffffu, gsum, off);
            }
            if ((lane & 3) == 0) {
                int rloc = wm * 32 + mt * 16 + half * 8 + (lane >> 2);
                esm[rloc * 4 + wn] = esum;
                gsm[rloc * 4 + wn] = gsum;
            }
        }
    }
    __syncthreads();
    if (tid < 64) {
        float e = esm[tid * 4] + esm[tid * 4 + 1] + esm[tid * 4 + 2] + esm[tid * 4 + 3];
        float g = gsm[tid * 4] + gsm[tid * 4 + 1] + gsm[tid * 4 + 2] + gsm[tid * 4 + 3];
        atomicAdd(&g_E[b * HWN + p0 + tid], (double)e);
        atomicAdd(&g_G[b * HWN + p0 + tid], (double)g);
    }
}

// ---------------- fused gates + gather: 4 windows/block, float4 gather -------
__global__ __launch_bounds__(128) void out_kernel(const float* __restrict__ x,
                                                  const int* __restrict__ lidx,
                                                  float* __restrict__ out) {
    int bf0 = blockIdx.x * WPB;
    int t = threadIdx.x;
    int wid = t >> 5, lane = t & 31;
    __shared__ int   sidx[WPB][FSZ];
    __shared__ float sgate[WPB][FSZ];

    if (t < WPB * FSZ) {
        int w = t / FSZ, j = t - w * FSZ;
        int bf = bf0 + w;
        int f = bf % NF;
        sidx[w][j] = lidx[f * FSZ + j];
    }
    __syncthreads();

    if (t < WPB * FSZ) {
        int w = t / FSZ, tt = t - w * FSZ;
        int bf = bf0 + w;
        int b = bf / NF;
        int p = sidx[w][tt];
        const float* bandb = g_band + (size_t)b * NBAND * HWN;
        const float* Vb = g_V + b * HWN;
        float e[FSZ], vv[FSZ];
#pragma unroll
        for (int j = 0; j < FSZ; j++) {
            int q = sidx[w][j];
            int d = q - p;
            int di = ((d + 80) >> 5) - 2;
            int dj = d - di * 32;
            e[j]  = bandb[((di + 2) * 5 + dj + 2) * HWN + p];
            vv[j] = Vb[q];
        }
        float sumE = 0.f, sumEV = 0.f;
#pragma unroll
        for (int j = 0; j < FSZ; j++) { sumE += e[j]; sumEV += e[j] * vv[j]; }
        float num = (float)(g_G[b * HWN + p] - (double)sumEV);
        float den = (float)(g_E[b * HWN + p] - (double)sumE) + EPSV;
        sgate[w][tt] = num / den;
    }
    __syncthreads();

    // one warp per window; one float4 per lane covers the full 128-ch row
    int bf = bf0 + wid;
    int b = bf / NF;
    const float* xb = x + (size_t)b * HWN * CD;
    float4 o = make_float4(0.f, 0.f, 0.f, 0.f);
#pragma unroll
    for (int p = 0; p < FSZ; p++) {
        float gp = sgate[wid][p];
        float4 v = reinterpret_cast<const float4*>(xb + (size_t)sidx[wid][p] * CD)[lane];
        o.x += gp * v.x; o.y += gp * v.y; o.z += gp * v.z; o.w += gp * v.w;
    }
    reinterpret_cast<float4*>(out + (size_t)bf * CD)[lane] = o;
}

// ---------------- launch -----------------------------------------------------
extern "C" void kernel_launch(void* const* d_in, const int* in_sizes, int n_in,
                              void* d_out, int out_size) {
    const float* batch = (const float*)d_in[0];
    const float* Wq    = (const float*)d_in[1];
    const float* bq    = (const float*)d_in[2];
    const float* Wk    = (const float*)d_in[3];
    const float* bk    = (const float*)d_in[4];
    const float* wv    = (const float*)d_in[5];
    const float* bv    = (const float*)d_in[6];
    const int*   lidx  = (const int*)d_in[8];
    float* out = (float*)d_out;

    cudaFuncSetAttribute(gemm_proj_tc, cudaFuncAttributeMaxDynamicSharedMemorySize, PSM_TOTAL);
    cudaFuncSetAttribute(gemm_s_tc,    cudaFuncAttributeMaxDynamicSharedMemorySize, SSM_TOTAL);

    prep_kernel<<<160, 256>>>(Wq, Wk);
    gemm_proj_tc<<<dim3(64, 2), 256, PSM_TOTAL>>>(batch, bq, bk, wv, bv);
    gemm_s_tc<<<dim3(8, 16, NB), 256, SSM_TOTAL>>>();
    out_kernel<<<NB * NF / WPB, 128>>>(batch, lidx, out);
}

// round 16
// speedup vs baseline: 1.4948x; 1.4948x over previous
#include <cuda_runtime.h>
#include <cuda_bf16.h>
#include <cstdint>
#include <math.h>

#define NB 8
#define HWN 1024
#define CD 128
#define NF 900
#define FSZ 9
#define EPSV 1e-5f
#define ROWB 272          // padded row stride in bytes (136 bf16) -> conflict-free ldmatrix
#define NBAND 25
#define WPB 4             // windows per out-block

// ---------------- scratch (device globals; allocation forbidden) ------------
__device__ __nv_bfloat16 g_Wqh[CD * CD];
__device__ __nv_bfloat16 g_Wql[CD * CD];
__device__ __nv_bfloat16 g_Wkh[CD * CD];
__device__ __nv_bfloat16 g_Wkl[CD * CD];
__device__ __nv_bfloat16 g_Qh[NB * HWN * CD];
__device__ __nv_bfloat16 g_Ql[NB * HWN * CD];
__device__ __nv_bfloat16 g_Kh[NB * HWN * CD];
__device__ __nv_bfloat16 g_Kl[NB * HWN * CD];
__device__ float  g_V[NB * HWN];
__device__ float  g_band[NB * NBAND * HWN];      // exp(S[p, p+delta]) banded, 800KB
__device__ double g_E[NB * HWN];
__device__ double g_G[NB * HWN];

// ---- proj smem layout (128x128 tiles), total 147456, 1 CTA/SM ----
#define PTILEB (128 * ROWB)
#define PSM_AUX  0
#define PSM_AH   8192
#define PSM_AL   (PSM_AH + PTILEB)
#define PSM_BH   (PSM_AL + PTILEB)
#define PSM_BL   (PSM_BH + PTILEB)
#define PSM_TOTAL (PSM_BL + PTILEB)

// ---- gemm_s smem layout (A 64-row, B 128-row), total 108544 -> 2 CTA/SM ----
#define ATILEB (64 * ROWB)
#define BTILEB (128 * ROWB)
#define SSM_AUX  0
#define SSM_ERED 512
#define SSM_GRED (SSM_ERED + 64 * 4 * 4)
#define SSM_AH   4096
#define SSM_AL   (SSM_AH + ATILEB)
#define SSM_BH   (SSM_AL + ATILEB)
#define SSM_BL   (SSM_BH + BTILEB)
#define SSM_TOTAL (SSM_BL + BTILEB)

extern __shared__ char smx[];

// ---------------- helpers ----------------------------------------------------
__device__ __forceinline__ uint32_t smem_u32(const void* p) {
    uint32_t a;
    asm("{ .reg .u64 t; cvta.to.shared.u64 t, %1; cvt.u32.u64 %0, t; }" : "=r"(a) : "l"(p));
    return a;
}
__device__ __forceinline__ void ldsm4(uint32_t* r, uint32_t addr) {
    asm volatile("ldmatrix.sync.aligned.m8n8.x4.shared.b16 {%0,%1,%2,%3}, [%4];"
                 : "=r"(r[0]), "=r"(r[1]), "=r"(r[2]), "=r"(r[3]) : "r"(addr));
}
__device__ __forceinline__ void ldsm2(uint32_t* r, uint32_t addr) {
    asm volatile("ldmatrix.sync.aligned.m8n8.x2.shared.b16 {%0,%1}, [%2];"
                 : "=r"(r[0]), "=r"(r[1]) : "r"(addr));
}
__device__ __forceinline__ void mma_bf16(float* d, const uint32_t* a, const uint32_t* b) {
    asm volatile("mma.sync.aligned.m16n8k16.row.col.f32.bf16.bf16.f32 "
                 "{%0,%1,%2,%3}, {%4,%5,%6,%7}, {%8,%9}, {%0,%1,%2,%3};"
                 : "+f"(d[0]), "+f"(d[1]), "+f"(d[2]), "+f"(d[3])
                 : "r"(a[0]), "r"(a[1]), "r"(a[2]), "r"(a[3]), "r"(b[0]), "r"(b[1]));
}

// sync copy (proj): [128][128] bf16 tile into padded smem
__device__ __forceinline__ void copy_tile(char* sm, const __nv_bfloat16* __restrict__ src, int tid) {
#pragma unroll
    for (int j = 0; j < 8; j++) {
        int idx = tid + j * 256;
        int row = idx >> 4;
        int c   = idx & 15;
        uint4 v = reinterpret_cast<const uint4*>(src + (size_t)row * CD)[c];
        *reinterpret_cast<uint4*>(sm + row * ROWB + c * 16) = v;
    }
}

// async copy (gemm_s): [rows][128] bf16 tile into padded smem via cp.async
__device__ __forceinline__ void copy_tile_async(uint32_t smdst, const __nv_bfloat16* __restrict__ src,
                                                int rows, int tid) {
    int chunks = rows * 16;
    for (int j = tid; j < chunks; j += 256) {
        int row = j >> 4, c = j & 15;
        uint32_t d = smdst + row * ROWB + c * 16;
        const void* g = src + (size_t)row * CD + c * 8;
        asm volatile("cp.async.cg.shared.global [%0], [%1], 16;" :: "r"(d), "l"(g));
    }
}

// ---------------- proj mainloop: 128x128 tiles, warp tile 64x32 --------------
__device__ __forceinline__ void mma_triple128(uint32_t sb, int wm, int wn, int lane,
                                              float acc[4][4][4]) {
    uint32_t arow = (wm * 64 + (lane & 15)) * ROWB + (lane >> 4) * 16;
    uint32_t brow = (wn * 32 + (lane & 7)) * ROWB + ((lane >> 3) & 1) * 16;
    uint32_t ah_b = sb + PSM_AH + arow, al_b = sb + PSM_AL + arow;
    uint32_t bh_b = sb + PSM_BH + brow, bl_b = sb + PSM_BL + brow;
#pragma unroll
    for (int kk = 0; kk < 8; kk++) {
        uint32_t kb = kk * 32;
        uint32_t ah[4][4], al[4][4], bh[4][2], bl[4][2];
#pragma unroll
        for (int mt = 0; mt < 4; mt++) {
            ldsm4(ah[mt], ah_b + mt * 16 * ROWB + kb);
            ldsm4(al[mt], al_b + mt * 16 * ROWB + kb);
        }
#pragma unroll
        for (int nt = 0; nt < 4; nt++) {
            ldsm2(bh[nt], bh_b + nt * 8 * ROWB + kb);
            ldsm2(bl[nt], bl_b + nt * 8 * ROWB + kb);
        }
#pragma unroll
        for (int mt = 0; mt < 4; mt++)
#pragma unroll
            for (int nt = 0; nt < 4; nt++) {
                mma_bf16(acc[mt][nt], ah[mt], bh[nt]);
                mma_bf16(acc[mt][nt], ah[mt], bl[nt]);
                mma_bf16(acc[mt][nt], al[mt], bh[nt]);
            }
    }
}

// ---------------- gemm_s mainloop: A 64-row, warp tile 32x32, merged 3-term --
__device__ __forceinline__ void mma_triple64(uint32_t sb, int wm, int wn, int lane,
                                             float acc[2][4][4]) {
    uint32_t arow = (wm * 32 + (lane & 15)) * ROWB + (lane >> 4) * 16;
    uint32_t brow = (wn * 32 + (lane & 7)) * ROWB + ((lane >> 3) & 1) * 16;
    uint32_t ah_b = sb + SSM_AH + arow, al_b = sb + SSM_AL + arow;
    uint32_t bh_b = sb + SSM_BH + brow, bl_b = sb + SSM_BL + brow;
#pragma unroll
    for (int kk = 0; kk < 8; kk++) {
        uint32_t kb = kk * 32;
        uint32_t ah[2][4], al[2][4], bh[4][2], bl[4][2];
#pragma unroll
        for (int mt = 0; mt < 2; mt++) {
            ldsm4(ah[mt], ah_b + mt * 16 * ROWB + kb);
            ldsm4(al[mt], al_b + mt * 16 * ROWB + kb);
        }
#pragma unroll
        for (int nt = 0; nt < 4; nt++) {
            ldsm2(bh[nt], bh_b + nt * 8 * ROWB + kb);
            ldsm2(bl[nt], bl_b + nt * 8 * ROWB + kb);
        }
#pragma unroll
        for (int mt = 0; mt < 2; mt++)
#pragma unroll
            for (int nt = 0; nt < 4; nt++) {
                mma_bf16(acc[mt][nt], ah[mt], bh[nt]);
                mma_bf16(acc[mt][nt], ah[mt], bl[nt]);
                mma_bf16(acc[mt][nt], al[mt], bh[nt]);
            }
    }
}

// ---------------- small prep: split W, zero E/G ------------------------------
__global__ void prep_kernel(const float* __restrict__ Wq, const float* __restrict__ Wk) {
    int blk = blockIdx.x;
    int t = threadIdx.x;
    if (blk < 64) {
        int i = blk * 256 + t;
        float v = Wq[i];
        __nv_bfloat16 h = __float2bfloat16(v);
        g_Wqh[i] = h;
        g_Wql[i] = __float2bfloat16(v - __bfloat162float(h));
    } else if (blk < 128) {
        int i = (blk - 64) * 256 + t;
        float v = Wk[i];
        __nv_bfloat16 h = __float2bfloat16(v);
        g_Wkh[i] = h;
        g_Wkl[i] = __float2bfloat16(v - __bfloat162float(h));
    } else {
        int i = (blk - 128) * 256 + t;
        g_E[i] = 0.0;
        g_G[i] = 0.0;
    }
}

// ---------------- projection GEMM (fp32 in, inline split, fused V) -----------
// blockIdx.x: row tile (64), blockIdx.y: 0 = Q (computes V), 1 = K
__global__ __launch_bounds__(256, 1) void gemm_proj_tc(const float* __restrict__ batch,
                                                       const float* __restrict__ bq,
                                                       const float* __restrict__ bk,
                                                       const float* __restrict__ wv,
                                                       const float* __restrict__ bv) {
    uint32_t sb = smem_u32(smx);
    int tid = threadIdx.x;
    int wid = tid >> 5, lane = tid & 31;
    int wm = wid & 1, wn = wid >> 1;
    int row0 = blockIdx.x * 128;
    bool isK = blockIdx.y != 0;

    const __nv_bfloat16* Wh = isK ? g_Wkh : g_Wqh;
    const __nv_bfloat16* Wl = isK ? g_Wkl : g_Wql;
    const float* bias = isK ? bk : bq;
    __nv_bfloat16* Oh = isK ? g_Kh : g_Qh;
    __nv_bfloat16* Ol = isK ? g_Kl : g_Ql;

    const float* xsrc = batch + (size_t)row0 * CD;
    float4 wv4;
    if (!isK) wv4 = reinterpret_cast<const float4*>(wv)[lane];
#pragma unroll
    for (int j = 0; j < 16; j++) {
        int idx = tid + j * 256;
        int row = idx >> 5;
        int c4  = idx & 31;
        float4 v = reinterpret_cast<const float4*>(xsrc + (size_t)row * CD)[c4];
        __nv_bfloat16 h0 = __float2bfloat16(v.x), h1 = __float2bfloat16(v.y);
        __nv_bfloat16 h2 = __float2bfloat16(v.z), h3 = __float2bfloat16(v.w);
        __nv_bfloat162 ph0, ph1, pl0, pl1;
        ph0.x = h0; ph0.y = h1; ph1.x = h2; ph1.y = h3;
        pl0.x = __float2bfloat16(v.x - __bfloat162float(h0));
        pl0.y = __float2bfloat16(v.y - __bfloat162float(h1));
        pl1.x = __float2bfloat16(v.z - __bfloat162float(h2));
        pl1.y = __float2bfloat16(v.w - __bfloat162float(h3));
        uint2 hh, ll;
        hh.x = *reinterpret_cast<uint32_t*>(&ph0); hh.y = *reinterpret_cast<uint32_t*>(&ph1);
        ll.x = *reinterpret_cast<uint32_t*>(&pl0); ll.y = *reinterpret_cast<uint32_t*>(&pl1);
        *reinterpret_cast<uint2*>(smx + PSM_AH + row * ROWB + c4 * 8) = hh;
        *reinterpret_cast<uint2*>(smx + PSM_AL + row * ROWB + c4 * 8) = ll;
        if (!isK) {
            float s = v.x * wv4.x + v.y * wv4.y + v.z * wv4.z + v.w * wv4.w;
#pragma unroll
            for (int off = 16; off; off >>= 1) s += __shfl_xor_sync(0xffffffffu, s, off);
            if (lane == 0) g_V[row0 + row] = s + bv[0];
        }
    }
    copy_tile(smx + PSM_BH, Wh, tid);
    copy_tile(smx + PSM_BL, Wl, tid);
    if (tid < 128) *reinterpret_cast<float*>(smx + PSM_AUX + tid * 4) = bias[tid];
    __syncthreads();

    float acc[4][4][4];
#pragma unroll
    for (int mt = 0; mt < 4; mt++)
#pragma unroll
        for (int nt = 0; nt < 4; nt++)
#pragma unroll
            for (int i = 0; i < 4; i++) acc[mt][nt][i] = 0.f;

    mma_triple128(sb, wm, wn, lane, acc);

    const float* bs = reinterpret_cast<const float*>(smx + PSM_AUX);
#pragma unroll
    for (int mt = 0; mt < 4; mt++) {
        int rlo = row0 + wm * 64 + mt * 16 + (lane >> 2);
#pragma unroll
        for (int nt = 0; nt < 4; nt++) {
            int col = wn * 32 + nt * 8 + (lane & 3) * 2;
            float b0 = bs[col], b1 = bs[col + 1];
#pragma unroll
            for (int half = 0; half < 2; half++) {
                int row = rlo + half * 8;
                float v0 = acc[mt][nt][half * 2 + 0] + b0;
                float v1 = acc[mt][nt][half * 2 + 1] + b1;
                __nv_bfloat16 h0 = __float2bfloat16(v0);
                __nv_bfloat16 h1 = __float2bfloat16(v1);
                __nv_bfloat162 ph; ph.x = h0; ph.y = h1;
                __nv_bfloat162 pl;
                pl.x = __float2bfloat16(v0 - __bfloat162float(h0));
                pl.y = __float2bfloat16(v1 - __bfloat162float(h1));
                *reinterpret_cast<uint32_t*>(Oh + (size_t)row * CD + col) =
                    *reinterpret_cast<uint32_t*>(&ph);
                *reinterpret_cast<uint32_t*>(Ol + (size_t)row * CD + col) =
                    *reinterpret_cast<uint32_t*>(&pl);
            }
        }
    }
}

// ---------------- E/G row sums + banded capture; M=64 tile, 2 CTA/SM ---------
// grid (8 qtile, 16 ptile, 8 batch)
__global__ __launch_bounds__(256, 2) void gemm_s_tc() {
    uint32_t sb = smem_u32(smx);
    int tid = threadIdx.x;
    int wid = tid >> 5, lane = tid & 31;
    int wm = wid & 1, wn = wid >> 1;
    int b  = blockIdx.z;
    int q0 = blockIdx.x * 128, p0 = blockIdx.y * 64;

    size_t abase = ((size_t)b * HWN + p0) * CD;
    size_t bbase = ((size_t)b * HWN + q0) * CD;
    copy_tile_async(sb + SSM_AH, g_Qh + abase, 64, tid);
    copy_tile_async(sb + SSM_AL, g_Ql + abase, 64, tid);
    copy_tile_async(sb + SSM_BH, g_Kh + bbase, 128, tid);
    copy_tile_async(sb + SSM_BL, g_Kl + bbase, 128, tid);
    asm volatile("cp.async.commit_group;" ::: "memory");
    if (tid < 128) *reinterpret_cast<float*>(smx + SSM_AUX + tid * 4) = g_V[b * HWN + q0 + tid];
    asm volatile("cp.async.wait_group 0;" ::: "memory");
    __syncthreads();

    float acc[2][4][4];
#pragma unroll
    for (int mt = 0; mt < 2; mt++)
#pragma unroll
        for (int nt = 0; nt < 4; nt++)
#pragma unroll
            for (int i = 0; i < 4; i++) acc[mt][nt][i] = 0.f;

    mma_triple64(sb, wm, wn, lane, acc);

    const float* Vs = reinterpret_cast<const float*>(smx + SSM_AUX);
    float* esm = reinterpret_cast<float*>(smx + SSM_ERED);
    float* gsm = reinterpret_cast<float*>(smx + SSM_GRED);
    float* bandb = g_band + (size_t)b * NBAND * HWN;
    int tdiff = q0 - p0;
    bool band_tile = (tdiff >= -194 && tdiff <= 130);

#pragma unroll
    for (int mt = 0; mt < 2; mt++) {
#pragma unroll
        for (int half = 0; half < 2; half++) {
            int p = p0 + wm * 32 + mt * 16 + half * 8 + (lane >> 2);
            float esum = 0.f, gsum = 0.f;
#pragma unroll
            for (int nt = 0; nt < 4; nt++) {
                int col = wn * 32 + nt * 8 + (lane & 3) * 2;
                float e0 = __expf(acc[mt][nt][half * 2 + 0]);
                float e1 = __expf(acc[mt][nt][half * 2 + 1]);
                esum += e0 + e1;
                gsum += e0 * Vs[col] + e1 * Vs[col + 1];
                if (band_tile) {
                    int q = q0 + col;
#pragma unroll
                    for (int u = 0; u < 2; u++) {
                        int d = q + u - p;
                        int di = ((d + 80) >> 5) - 2;
                        int dj = d - di * 32;
                        if (di >= -2 && di <= 2 && dj >= -2 && dj <= 2)
                            bandb[((di + 2) * 5 + dj + 2) * HWN + p] = u ? e1 : e0;
                    }
                }
            }
#pragma unroll
            for (int off = 1; off <= 2; off <<= 1) {
                esum += __shfl_xor_sync(0xffffffffu, esum, off);
                gsum += __shfl_xor_sync(0xffffffffu, gsum, off);
            }
            if ((lane & 3) == 0) {
                int rloc = wm * 32 + mt * 16 + half * 8 + (lane >> 2);
                esm[rloc * 4 + wn] = esum;
                gsm[rloc * 4 + wn] = gsum;
            }
        }
    }
    __syncthreads();
    if (tid < 64) {
        float e = esm[tid * 4] + esm[tid * 4 + 1] + esm[tid * 4 + 2] + esm[tid * 4 + 3];
        float g = gsm[tid * 4] + gsm[tid * 4 + 1] + gsm[tid * 4 + 2] + gsm[tid * 4 + 3];
        atomicAdd(&g_E[b * HWN + p0 + tid], (double)e);
        atomicAdd(&g_G[b * HWN + p0 + tid], (double)g);
    }
}

// ---------------- fused gates + gather: 4 windows/block ----------------------
__global__ __launch_bounds__(128) void out_kernel(const float* __restrict__ x,
                                                  const int* __restrict__ lidx,
                                                  float* __restrict__ out) {
    int bf0 = blockIdx.x * WPB;
    int t = threadIdx.x;
    int wid = t >> 5, lane = t & 31;
    __shared__ int   sidx[WPB][FSZ];
    __shared__ float sgate[WPB][FSZ];

    if (t < WPB * FSZ) {
        int w = t / FSZ, j = t - w * FSZ;
        int bf = bf0 + w;
        int f = bf % NF;
        sidx[w][j] = lidx[f * FSZ + j];
    }
    __syncthreads();

    if (t < WPB * FSZ) {
        int w = t / FSZ, tt = t - w * FSZ;
        int bf = bf0 + w;
        int b = bf / NF;
        int p = sidx[w][tt];
        const float* bandb = g_band + (size_t)b * NBAND * HWN;
        const float* Vb = g_V + b * HWN;
        float e[FSZ], vv[FSZ];
#pragma unroll
        for (int j = 0; j < FSZ; j++) {
            int q = sidx[w][j];
            int d = q - p;
            int di = ((d + 80) >> 5) - 2;
            int dj = d - di * 32;
            e[j]  = bandb[((di + 2) * 5 + dj + 2) * HWN + p];
            vv[j] = Vb[q];
        }
        float sumE = 0.f, sumEV = 0.f;
#pragma unroll
        for (int j = 0; j < FSZ; j++) { sumE += e[j]; sumEV += e[j] * vv[j]; }
        float num = (float)(g_G[b * HWN + p] - (double)sumEV);
        float den = (float)(g_E[b * HWN + p] - (double)sumE) + EPSV;
        sgate[w][tt] = num / den;
    }
    __syncthreads();

    int bf = bf0 + wid;
    int b = bf / NF;
    const float* xb = x + (size_t)b * HWN * CD;
    float g[FSZ];
    const float* xr[FSZ];
#pragma unroll
    for (int p = 0; p < FSZ; p++) {
        g[p] = sgate[wid][p];
        xr[p] = xb + (size_t)sidx[wid][p] * CD;
    }
#pragma unroll
    for (int ch = 0; ch < 4; ch++) {
        int c = ch * 32 + lane;
        float o = 0.f;
#pragma unroll
        for (int p = 0; p < FSZ; p++) o += g[p] * xr[p][c];
        out[(size_t)bf * CD + c] = o;
    }
}

// ---------------- launch -----------------------------------------------------
extern "C" void kernel_launch(void* const* d_in, const int* in_sizes, int n_in,
                              void* d_out, int out_size) {
    const float* batch = (const float*)d_in[0];
    const float* Wq    = (const float*)d_in[1];
    const float* bq    = (const float*)d_in[2];
    const float* Wk    = (const float*)d_in[3];
    const float* bk    = (const float*)d_in[4];
    const float* wv    = (const float*)d_in[5];
    const float* bv    = (const float*)d_in[6];
    const int*   lidx  = (const int*)d_in[8];
    float* out = (float*)d_out;

    cudaFuncSetAttribute(gemm_proj_tc, cudaFuncAttributeMaxDynamicSharedMemorySize, PSM_TOTAL);
    cudaFuncSetAttribute(gemm_s_tc,    cudaFuncAttributeMaxDynamicSharedMemorySize, SSM_TOTAL);

    prep_kernel<<<160, 256>>>(Wq, Wk);
    gemm_proj_tc<<<dim3(64, 2), 256, PSM_TOTAL>>>(batch, bq, bk, wv, bv);
    gemm_s_tc<<<dim3(8, 16, NB), 256, SSM_TOTAL>>>();
    out_kernel<<<NB * NF / WPB, 128>>>(batch, lidx, out);
}

// round 17
// speedup vs baseline: 1.6959x; 1.1345x over previous
#include <cuda_runtime.h>
#include <cuda_bf16.h>
#include <cuda_fp16.h>
#include <cstdint>
#include <math.h>

#define NB 8
#define HWN 1024
#define CD 128
#define NF 900
#define FSZ 9
#define EPSV 1e-5f
#define ROWB 272          // padded row stride in bytes (136 elems of 2B) -> conflict-free ldmatrix
#define NBAND 25
#define WPB 4             // windows per out-block

// ---------------- scratch (device globals; allocation forbidden) ------------
__device__ __nv_bfloat16 g_Wqh[CD * CD];
__device__ __nv_bfloat16 g_Wql[CD * CD];
__device__ __nv_bfloat16 g_Wkh[CD * CD];
__device__ __nv_bfloat16 g_Wkl[CD * CD];
__device__ __half g_Qf[NB * HWN * CD];           // fp16 single-rounded Q
__device__ __half g_Kh[NB * HWN * CD];           // fp16 hi(K)
__device__ __half g_Kl[NB * HWN * CD];           // fp16 lo(K)
__device__ float  g_V[NB * HWN];
__device__ float  g_band[NB * NBAND * HWN];      // exp(S[p, p+delta]) banded, 800KB
__device__ double g_E[NB * HWN];
__device__ double g_G[NB * HWN];

// ---- proj smem layout (128x128 tiles), total 147456, 1 CTA/SM ----
#define PTILEB (128 * ROWB)
#define PSM_AUX  0
#define PSM_AH   8192
#define PSM_AL   (PSM_AH + PTILEB)
#define PSM_BH   (PSM_AL + PTILEB)
#define PSM_BL   (PSM_BH + PTILEB)
#define PSM_TOTAL (PSM_BL + PTILEB)

// ---- gemm_s smem layout (A 64-row fp16, Kh/Kl 128-row), total 91136 ----
#define ATILEB (64 * ROWB)
#define BTILEB (128 * ROWB)
#define SSM_AUX  0
#define SSM_ERED 512
#define SSM_GRED (SSM_ERED + 64 * 4 * 4)
#define SSM_A    4096
#define SSM_BH   (SSM_A + ATILEB)
#define SSM_BL   (SSM_BH + BTILEB)
#define SSM_TOTAL (SSM_BL + BTILEB)

extern __shared__ char smx[];

// ---------------- helpers ----------------------------------------------------
__device__ __forceinline__ uint32_t smem_u32(const void* p) {
    uint32_t a;
    asm("{ .reg .u64 t; cvta.to.shared.u64 t, %1; cvt.u32.u64 %0, t; }" : "=r"(a) : "l"(p));
    return a;
}
__device__ __forceinline__ void ldsm4(uint32_t* r, uint32_t addr) {
    asm volatile("ldmatrix.sync.aligned.m8n8.x4.shared.b16 {%0,%1,%2,%3}, [%4];"
                 : "=r"(r[0]), "=r"(r[1]), "=r"(r[2]), "=r"(r[3]) : "r"(addr));
}
__device__ __forceinline__ void ldsm2(uint32_t* r, uint32_t addr) {
    asm volatile("ldmatrix.sync.aligned.m8n8.x2.shared.b16 {%0,%1}, [%2];"
                 : "=r"(r[0]), "=r"(r[1]) : "r"(addr));
}
__device__ __forceinline__ void mma_bf16(float* d, const uint32_t* a, const uint32_t* b) {
    asm volatile("mma.sync.aligned.m16n8k16.row.col.f32.bf16.bf16.f32 "
                 "{%0,%1,%2,%3}, {%4,%5,%6,%7}, {%8,%9}, {%0,%1,%2,%3};"
                 : "+f"(d[0]), "+f"(d[1]), "+f"(d[2]), "+f"(d[3])
                 : "r"(a[0]), "r"(a[1]), "r"(a[2]), "r"(a[3]), "r"(b[0]), "r"(b[1]));
}
__device__ __forceinline__ void mma_fp16(float* d, const uint32_t* a, const uint32_t* b) {
    asm volatile("mma.sync.aligned.m16n8k16.row.col.f32.f16.f16.f32 "
                 "{%0,%1,%2,%3}, {%4,%5,%6,%7}, {%8,%9}, {%0,%1,%2,%3};"
                 : "+f"(d[0]), "+f"(d[1]), "+f"(d[2]), "+f"(d[3])
                 : "r"(a[0]), "r"(a[1]), "r"(a[2]), "r"(a[3]), "r"(b[0]), "r"(b[1]));
}

// sync copy (proj): [128][128] 2B-elem tile into padded smem
__device__ __forceinline__ void copy_tile(char* sm, const void* __restrict__ src, int tid) {
#pragma unroll
    for (int j = 0; j < 8; j++) {
        int idx = tid + j * 256;
        int row = idx >> 4;
        int c   = idx & 15;
        uint4 v = *reinterpret_cast<const uint4*>((const char*)src + (size_t)row * 256 + c * 16);
        *reinterpret_cast<uint4*>(sm + row * ROWB + c * 16) = v;
    }
}

// async copy (gemm_s): [rows][128] 2B-elem tile into padded smem via cp.async
__device__ __forceinline__ void copy_tile_async(uint32_t smdst, const void* __restrict__ src,
                                                int rows, int tid) {
    int chunks = rows * 16;
    for (int j = tid; j < chunks; j += 256) {
        int row = j >> 4, c = j & 15;
        uint32_t d = smdst + row * ROWB + c * 16;
        const void* g = (const char*)src + (size_t)row * 256 + c * 16;
        asm volatile("cp.async.cg.shared.global [%0], [%1], 16;" :: "r"(d), "l"(g));
    }
}

// ---------------- proj mainloop: 128x128 tiles, warp tile 64x32, bf16 3-term -
__device__ __forceinline__ void mma_triple128(uint32_t sb, int wm, int wn, int lane,
                                              float acc[4][4][4]) {
    uint32_t arow = (wm * 64 + (lane & 15)) * ROWB + (lane >> 4) * 16;
    uint32_t brow = (wn * 32 + (lane & 7)) * ROWB + ((lane >> 3) & 1) * 16;
    uint32_t ah_b = sb + PSM_AH + arow, al_b = sb + PSM_AL + arow;
    uint32_t bh_b = sb + PSM_BH + brow, bl_b = sb + PSM_BL + brow;
#pragma unroll
    for (int kk = 0; kk < 8; kk++) {
        uint32_t kb = kk * 32;
        uint32_t ah[4][4], al[4][4], bh[4][2], bl[4][2];
#pragma unroll
        for (int mt = 0; mt < 4; mt++) {
            ldsm4(ah[mt], ah_b + mt * 16 * ROWB + kb);
            ldsm4(al[mt], al_b + mt * 16 * ROWB + kb);
        }
#pragma unroll
        for (int nt = 0; nt < 4; nt++) {
            ldsm2(bh[nt], bh_b + nt * 8 * ROWB + kb);
            ldsm2(bl[nt], bl_b + nt * 8 * ROWB + kb);
        }
#pragma unroll
        for (int mt = 0; mt < 4; mt++)
#pragma unroll
            for (int nt = 0; nt < 4; nt++) {
                mma_bf16(acc[mt][nt], ah[mt], bh[nt]);
                mma_bf16(acc[mt][nt], ah[mt], bl[nt]);
                mma_bf16(acc[mt][nt], al[mt], bh[nt]);
            }
    }
}

// ---------------- gemm_s mainloop: fp16 2-term (A single, B hi/lo) -----------
__device__ __forceinline__ void mma_duo64(uint32_t sb, int wm, int wn, int lane,
                                          float acc[2][4][4]) {
    uint32_t arow = (wm * 32 + (lane & 15)) * ROWB + (lane >> 4) * 16;
    uint32_t brow = (wn * 32 + (lane & 7)) * ROWB + ((lane >> 3) & 1) * 16;
    uint32_t a_b  = sb + SSM_A + arow;
    uint32_t bh_b = sb + SSM_BH + brow, bl_b = sb + SSM_BL + brow;
#pragma unroll
    for (int kk = 0; kk < 8; kk++) {
        uint32_t kb = kk * 32;
        uint32_t ah[2][4], bh[4][2], bl[4][2];
#pragma unroll
        for (int mt = 0; mt < 2; mt++) ldsm4(ah[mt], a_b + mt * 16 * ROWB + kb);
#pragma unroll
        for (int nt = 0; nt < 4; nt++) {
            ldsm2(bh[nt], bh_b + nt * 8 * ROWB + kb);
            ldsm2(bl[nt], bl_b + nt * 8 * ROWB + kb);
        }
#pragma unroll
        for (int mt = 0; mt < 2; mt++)
#pragma unroll
            for (int nt = 0; nt < 4; nt++) {
                mma_fp16(acc[mt][nt], ah[mt], bh[nt]);
                mma_fp16(acc[mt][nt], ah[mt], bl[nt]);
            }
    }
}

// ---------------- small prep: split W (bf16), zero E/G -----------------------
__global__ void prep_kernel(const float* __restrict__ Wq, const float* __restrict__ Wk) {
    int blk = blockIdx.x;
    int t = threadIdx.x;
    if (blk < 64) {
        int i = blk * 256 + t;
        float v = Wq[i];
        __nv_bfloat16 h = __float2bfloat16(v);
        g_Wqh[i] = h;
        g_Wql[i] = __float2bfloat16(v - __bfloat162float(h));
    } else if (blk < 128) {
        int i = (blk - 64) * 256 + t;
        float v = Wk[i];
        __nv_bfloat16 h = __float2bfloat16(v);
        g_Wkh[i] = h;
        g_Wkl[i] = __float2bfloat16(v - __bfloat162float(h));
    } else {
        int i = (blk - 128) * 256 + t;
        g_E[i] = 0.0;
        g_G[i] = 0.0;
    }
}

// ---------------- projection GEMM (fp32 in, inline split, fused V) -----------
// blockIdx.x: row tile (64), blockIdx.y: 0 = Q (computes V; emits fp16 single),
//                                        1 = K (emits fp16 hi/lo)
__global__ __launch_bounds__(256, 1) void gemm_proj_tc(const float* __restrict__ batch,
                                                       const float* __restrict__ bq,
                                                       const float* __restrict__ bk,
                                                       const float* __restrict__ wv,
                                                       const float* __restrict__ bv) {
    uint32_t sb = smem_u32(smx);
    int tid = threadIdx.x;
    int wid = tid >> 5, lane = tid & 31;
    int wm = wid & 1, wn = wid >> 1;
    int row0 = blockIdx.x * 128;
    bool isK = blockIdx.y != 0;

    const __nv_bfloat16* Wh = isK ? g_Wkh : g_Wqh;
    const __nv_bfloat16* Wl = isK ? g_Wkl : g_Wql;
    const float* bias = isK ? bk : bq;

    const float* xsrc = batch + (size_t)row0 * CD;
    float4 wv4;
    if (!isK) wv4 = reinterpret_cast<const float4*>(wv)[lane];
#pragma unroll
    for (int j = 0; j < 16; j++) {
        int idx = tid + j * 256;
        int row = idx >> 5;
        int c4  = idx & 31;
        float4 v = reinterpret_cast<const float4*>(xsrc + (size_t)row * CD)[c4];
        __nv_bfloat16 h0 = __float2bfloat16(v.x), h1 = __float2bfloat16(v.y);
        __nv_bfloat16 h2 = __float2bfloat16(v.z), h3 = __float2bfloat16(v.w);
        __nv_bfloat162 ph0, ph1, pl0, pl1;
        ph0.x = h0; ph0.y = h1; ph1.x = h2; ph1.y = h3;
        pl0.x = __float2bfloat16(v.x - __bfloat162float(h0));
        pl0.y = __float2bfloat16(v.y - __bfloat162float(h1));
        pl1.x = __float2bfloat16(v.z - __bfloat162float(h2));
        pl1.y = __float2bfloat16(v.w - __bfloat162float(h3));
        uint2 hh, ll;
        hh.x = *reinterpret_cast<uint32_t*>(&ph0); hh.y = *reinterpret_cast<uint32_t*>(&ph1);
        ll.x = *reinterpret_cast<uint32_t*>(&pl0); ll.y = *reinterpret_cast<uint32_t*>(&pl1);
        *reinterpret_cast<uint2*>(smx + PSM_AH + row * ROWB + c4 * 8) = hh;
        *reinterpret_cast<uint2*>(smx + PSM_AL + row * ROWB + c4 * 8) = ll;
        if (!isK) {
            float s = v.x * wv4.x + v.y * wv4.y + v.z * wv4.z + v.w * wv4.w;
#pragma unroll
            for (int off = 16; off; off >>= 1) s += __shfl_xor_sync(0xffffffffu, s, off);
            if (lane == 0) g_V[row0 + row] = s + bv[0];
        }
    }
    copy_tile(smx + PSM_BH, Wh, tid);
    copy_tile(smx + PSM_BL, Wl, tid);
    if (tid < 128) *reinterpret_cast<float*>(smx + PSM_AUX + tid * 4) = bias[tid];
    __syncthreads();

    float acc[4][4][4];
#pragma unroll
    for (int mt = 0; mt < 4; mt++)
#pragma unroll
        for (int nt = 0; nt < 4; nt++)
#pragma unroll
            for (int i = 0; i < 4; i++) acc[mt][nt][i] = 0.f;

    mma_triple128(sb, wm, wn, lane, acc);

    const float* bs = reinterpret_cast<const float*>(smx + PSM_AUX);
#pragma unroll
    for (int mt = 0; mt < 4; mt++) {
        int rlo = row0 + wm * 64 + mt * 16 + (lane >> 2);
#pragma unroll
        for (int nt = 0; nt < 4; nt++) {
            int col = wn * 32 + nt * 8 + (lane & 3) * 2;
            float b0 = bs[col], b1 = bs[col + 1];
#pragma unroll
            for (int half = 0; half < 2; half++) {
                int row = rlo + half * 8;
                float v0 = acc[mt][nt][half * 2 + 0] + b0;
                float v1 = acc[mt][nt][half * 2 + 1] + b1;
                if (!isK) {
                    __half2 p;
                    p.x = __float2half_rn(v0);
                    p.y = __float2half_rn(v1);
                    *reinterpret_cast<uint32_t*>(g_Qf + (size_t)row * CD + col) =
                        *reinterpret_cast<uint32_t*>(&p);
                } else {
                    __half h0 = __float2half_rn(v0);
                    __half h1 = __float2half_rn(v1);
                    __half2 ph; ph.x = h0; ph.y = h1;
                    __half2 pl;
                    pl.x = __float2half_rn(v0 - __half2float(h0));
                    pl.y = __float2half_rn(v1 - __half2float(h1));
                    *reinterpret_cast<uint32_t*>(g_Kh + (size_t)row * CD + col) =
                        *reinterpret_cast<uint32_t*>(&ph);
                    *reinterpret_cast<uint32_t*>(g_Kl + (size_t)row * CD + col) =
                        *reinterpret_cast<uint32_t*>(&pl);
                }
            }
        }
    }
}

// ---------------- E/G row sums + banded capture; M=64 tile, 2 CTA/SM ---------
// grid (8 qtile, 16 ptile, 8 batch); fp16 2-term mainloop
__global__ __launch_bounds__(256, 2) void gemm_s_tc() {
    uint32_t sb = smem_u32(smx);
    int tid = threadIdx.x;
    int wid = tid >> 5, lane = tid & 31;
    int wm = wid & 1, wn = wid >> 1;
    int b  = blockIdx.z;
    int q0 = blockIdx.x * 128, p0 = blockIdx.y * 64;

    size_t abase = ((size_t)b * HWN + p0) * CD;
    size_t bbase = ((size_t)b * HWN + q0) * CD;
    copy_tile_async(sb + SSM_A,  g_Qf + abase, 64, tid);
    copy_tile_async(sb + SSM_BH, g_Kh + bbase, 128, tid);
    copy_tile_async(sb + SSM_BL, g_Kl + bbase, 128, tid);
    asm volatile("cp.async.commit_group;" ::: "memory");
    if (tid < 128) *reinterpret_cast<float*>(smx + SSM_AUX + tid * 4) = g_V[b * HWN + q0 + tid];
    asm volatile("cp.async.wait_group 0;" ::: "memory");
    __syncthreads();

    float acc[2][4][4];
#pragma unroll
    for (int mt = 0; mt < 2; mt++)
#pragma unroll
        for (int nt = 0; nt < 4; nt++)
#pragma unroll
            for (int i = 0; i < 4; i++) acc[mt][nt][i] = 0.f;

    mma_duo64(sb, wm, wn, lane, acc);

    const float* Vs = reinterpret_cast<const float*>(smx + SSM_AUX);
    float* esm = reinterpret_cast<float*>(smx + SSM_ERED);
    float* gsm = reinterpret_cast<float*>(smx + SSM_GRED);
    float* bandb = g_band + (size_t)b * NBAND * HWN;
    int tdiff = q0 - p0;
    bool band_tile = (tdiff >= -194 && tdiff <= 130);

#pragma unroll
    for (int mt = 0; mt < 2; mt++) {
#pragma unroll
        for (int half = 0; half < 2; half++) {
            int p = p0 + wm * 32 + mt * 16 + half * 8 + (lane >> 2);
            float esum = 0.f, gsum = 0.f;
#pragma unroll
            for (int nt = 0; nt < 4; nt++) {
                int col = wn * 32 + nt * 8 + (lane & 3) * 2;
                float e0 = __expf(acc[mt][nt][half * 2 + 0]);
                float e1 = __expf(acc[mt][nt][half * 2 + 1]);
                esum += e0 + e1;
                gsum += e0 * Vs[col] + e1 * Vs[col + 1];
                if (band_tile) {
                    int q = q0 + col;
#pragma unroll
                    for (int u = 0; u < 2; u++) {
                        int d = q + u - p;
                        int di = ((d + 80) >> 5) - 2;
                        int dj = d - di * 32;
                        if (di >= -2 && di <= 2 && dj >= -2 && dj <= 2)
                            bandb[((di + 2) * 5 + dj + 2) * HWN + p] = u ? e1 : e0;
                    }
                }
            }
#pragma unroll
            for (int off = 1; off <= 2; off <<= 1) {
                esum += __shfl_xor_sync(0xffffffffu, esum, off);
                gsum += __shfl_xor_sync(0xffffffffu, gsum, off);
            }
            if ((lane & 3) == 0) {
                int rloc = wm * 32 + mt * 16 + half * 8 + (lane >> 2);
                esm[rloc * 4 + wn] = esum;
                gsm[rloc * 4 + wn] = gsum;
            }
        }
    }
    __syncthreads();
    if (tid < 64) {
        float e = esm[tid * 4] + esm[tid * 4 + 1] + esm[tid * 4 + 2] + esm[tid * 4 + 3];
        float g = gsm[tid * 4] + gsm[tid * 4 + 1] + gsm[tid * 4 + 2] + gsm[tid * 4 + 3];
        atomicAdd(&g_E[b * HWN + p0 + tid], (double)e);
        atomicAdd(&g_G[b * HWN + p0 + tid], (double)g);
    }
}

// ---------------- fused gates + gather: 4 windows/block ----------------------
__global__ __launch_bounds__(128) void out_kernel(const float* __restrict__ x,
                                                  const int* __restrict__ lidx,
                                                  float* __restrict__ out) {
    int bf0 = blockIdx.x * WPB;
    int t = threadIdx.x;
    int wid = t >> 5, lane = t & 31;
    __shared__ int   sidx[WPB][FSZ];
    __shared__ float sgate[WPB][FSZ];

    if (t < WPB * FSZ) {
        int w = t / FSZ, j = t - w * FSZ;
        int bf = bf0 + w;
        int f = bf % NF;
        sidx[w][j] = lidx[f * FSZ + j];
    }
    __syncthreads();

    if (t < WPB * FSZ) {
        int w = t / FSZ, tt = t - w * FSZ;
        int bf = bf0 + w;
        int b = bf / NF;
        int p = sidx[w][tt];
        const float* bandb = g_band + (size_t)b * NBAND * HWN;
        const float* Vb = g_V + b * HWN;
        float e[FSZ], vv[FSZ];
#pragma unroll
        for (int j = 0; j < FSZ; j++) {
            int q = sidx[w][j];
            int d = q - p;
            int di = ((d + 80) >> 5) - 2;
            int dj = d - di * 32;
            e[j]  = bandb[((di + 2) * 5 + dj + 2) * HWN + p];
            vv[j] = Vb[q];
        }
        float sumE = 0.f, sumEV = 0.f;
#pragma unroll
        for (int j = 0; j < FSZ; j++) { sumE += e[j]; sumEV += e[j] * vv[j]; }
        float num = (float)(g_G[b * HWN + p] - (double)sumEV);
        float den = (float)(g_E[b * HWN + p] - (double)sumE) + EPSV;
        sgate[w][tt] = num / den;
    }
    __syncthreads();

    int bf = bf0 + wid;
    int b = bf / NF;
    const float* xb = x + (size_t)b * HWN * CD;
    float g[FSZ];
    const float* xr[FSZ];
#pragma unroll
    for (int p = 0; p < FSZ; p++) {
        g[p] = sgate[wid][p];
        xr[p] = xb + (size_t)sidx[wid][p] * CD;
    }
#pragma unroll
    for (int ch = 0; ch < 4; ch++) {
        int c = ch * 32 + lane;
        float o = 0.f;
#pragma unroll
        for (int p = 0; p < FSZ; p++) o += g[p] * xr[p][c];
        out[(size_t)bf * CD + c] = o;
    }
}

// ---------------- launch -----------------------------------------------------
extern "C" void kernel_launch(void* const* d_in, const int* in_sizes, int n_in,
                              void* d_out, int out_size) {
    const float* batch = (const float*)d_in[0];
    const float* Wq    = (const float*)d_in[1];
    const float* bq    = (const float*)d_in[2];
    const float* Wk    = (const float*)d_in[3];
    const float* bk    = (const float*)d_in[4];
    const float* wv    = (const float*)d_in[5];
    const float* bv    = (const float*)d_in[6];
    const int*   lidx  = (const int*)d_in[8];
    float* out = (float*)d_out;

    cudaFuncSetAttribute(gemm_proj_tc, cudaFuncAttributeMaxDynamicSharedMemorySize, PSM_TOTAL);
    cudaFuncSetAttribute(gemm_s_tc,    cudaFuncAttributeMaxDynamicSharedMemorySize, SSM_TOTAL);

    prep_kernel<<<160, 256>>>(Wq, Wk);
    gemm_proj_tc<<<dim3(64, 2), 256, PSM_TOTAL>>>(batch, bq, bk, wv, bv);
    gemm_s_tc<<<dim3(8, 16, NB), 256, SSM_TOTAL>>>();
    out_kernel<<<NB * NF / WPB, 128>>>(batch, lidx, out);
}